// round 1
// baseline (speedup 1.0000x reference)
#include <cuda_runtime.h>
#include <cuda_bf16.h>
#include <cstddef>

// Problem constants
#define BB   64
#define TT   2048
#define HH   128
#define GG   384     // 3*H
#define DIN  18
#define DOUT 2
#define BTR  (BB*TT)           // 131072 rows

// ---------------------------------------------------------------------------
// Scratch (device globals; no allocation allowed)
// ---------------------------------------------------------------------------
static __device__ float g_xgF[(size_t)BTR * GG];   // 201 MB
static __device__ float g_xgR[(size_t)BTR * GG];   // 201 MB
static __device__ float g_h  [(size_t)BTR * 2*HH]; // 134 MB (h0, then reused for h1)

// ---------------------------------------------------------------------------
// Activation helpers (fp32)
// ---------------------------------------------------------------------------
__device__ __forceinline__ float sigf(float x) {
    return 1.0f / (1.0f + __expf(-x));
}
__device__ __forceinline__ float tanh_fast(float x) {
    float xc = fminf(fmaxf(x, -20.0f), 20.0f);
    float e  = __expf(-2.0f * xc);
    return (1.0f - e) / (1.0f + e);
}

// ---------------------------------------------------------------------------
// Generic fp32 GEMM:  C[M][N] = A[M][K] * B[N][K]^T + bias[N]
// 64x64 tile, BK=16, 256 threads, 4x4 outputs per thread.
// ---------------------------------------------------------------------------
__global__ __launch_bounds__(256) void gemm_tn_bias(
    const float* __restrict__ A, int lda,
    const float* __restrict__ Bw,        // [N][K] row-major
    const float* __restrict__ bias,      // [N]
    float* __restrict__ C, int ldc,
    int M, int N, int K)
{
    const int BM = 64, BN = 64, BK = 16;
    const int PAD = 8;                    // row stride 72 floats: 4-way store conflicts, 16B-aligned rows
    __shared__ __align__(16) float As[BK][BM + PAD];
    __shared__ __align__(16) float Bs[BK][BN + PAD];

    int tid = threadIdx.x;
    int tx = tid & 15;          // n group
    int ty = tid >> 4;          // m group
    int m0 = blockIdx.x * BM;
    int n0 = blockIdx.y * BN;

    float acc[4][4];
#pragma unroll
    for (int i = 0; i < 4; i++)
#pragma unroll
        for (int j = 0; j < 4; j++) acc[i][j] = 0.0f;

    int nkt = (K + BK - 1) / BK;
    for (int kt = 0; kt < nkt; kt++) {
        int k0 = kt * BK;
        // Load A tile: idx -> (m = idx/BK, k = idx%BK), coalesced along k per row
#pragma unroll
        for (int r = 0; r < 4; r++) {
            int idx = tid + r * 256;
            int m = idx >> 4;           // /16
            int k = idx & 15;
            float va = 0.0f, vb = 0.0f;
            if (k0 + k < K) {
                va = A[(size_t)(m0 + m) * lda + k0 + k];
                vb = Bw[(size_t)(n0 + m) * K + k0 + k];
            }
            As[k][m] = va;
            Bs[k][m] = vb;
        }
        __syncthreads();
#pragma unroll
        for (int k = 0; k < BK; k++) {
            float4 a = *(const float4*)&As[k][ty * 4];
            float4 b = *(const float4*)&Bs[k][tx * 4];
            float av[4] = {a.x, a.y, a.z, a.w};
            float bv[4] = {b.x, b.y, b.z, b.w};
#pragma unroll
            for (int i = 0; i < 4; i++)
#pragma unroll
                for (int j = 0; j < 4; j++)
                    acc[i][j] = fmaf(av[i], bv[j], acc[i][j]);
        }
        __syncthreads();
    }

#pragma unroll
    for (int i = 0; i < 4; i++) {
        int m = m0 + ty * 4 + i;
#pragma unroll
        for (int j = 0; j < 4; j++) {
            int n = n0 + tx * 4 + j;
            C[(size_t)m * ldc + n] = acc[i][j] + bias[n];
        }
    }
}

// ---------------------------------------------------------------------------
// GRU scan over T for one layer, both directions in one launch.
// grid = 128 blocks: blockIdx.x = b*2 + dir. 384 threads, one gate each.
// w_hh row (128 floats) register-resident per thread.
// out: [B][T][256], fwd at cols [0,128), bwd at [128,256).
// ---------------------------------------------------------------------------
__global__ __launch_bounds__(384, 1) void gru_scan(
    const float* __restrict__ xgF, const float* __restrict__ xgR,
    const float* __restrict__ whhF, const float* __restrict__ bhhF,
    const float* __restrict__ whhR, const float* __restrict__ bhhR,
    float* __restrict__ out)
{
    int bb  = blockIdx.x >> 1;
    int dir = blockIdx.x & 1;
    const float* xg  = dir ? xgR  : xgF;
    const float* whh = dir ? whhR : whhF;
    const float* bhh = dir ? bhhR : bhhF;

    int g = threadIdx.x;

    // Register-resident weight row
    float w[128];
    {
        const float4* wrow = (const float4*)(whh + (size_t)g * HH);
#pragma unroll
        for (int i = 0; i < 32; i++) {
            float4 v = wrow[i];
            w[4*i+0] = v.x; w[4*i+1] = v.y; w[4*i+2] = v.z; w[4*i+3] = v.w;
        }
    }
    float bh = bhh[g];

    __shared__ __align__(16) float hs[HH];
    __shared__ float gh[GG];
    if (g < HH) hs[g] = 0.0f;

    const size_t baseXG  = (size_t)bb * TT * GG;
    const size_t baseOut = (size_t)bb * TT * (2*HH) + (size_t)dir * HH;

    // Prefetch xg for first step
    float xr = 0.f, xz = 0.f, xn = 0.f;
    {
        int tt0 = dir ? (TT - 1) : 0;
        if (g < HH) {
            const float* p = xg + baseXG + (size_t)tt0 * GG;
            xr = p[g]; xz = p[g + HH]; xn = p[g + 2*HH];
        }
    }
    __syncthreads();

    for (int t = 0; t < TT; t++) {
        int tt = dir ? (TT - 1 - t) : t;

        // Issue prefetch for next step (latency hidden behind matvec)
        float nxr = 0.f, nxz = 0.f, nxn = 0.f;
        if (g < HH && t + 1 < TT) {
            int tn = dir ? (tt - 1) : (tt + 1);
            const float* p = xg + baseXG + (size_t)tn * GG;
            nxr = p[g]; nxz = p[g + HH]; nxn = p[g + 2*HH];
        }

        // gh[g] = dot(h, w_hh[g,:]) + b_hh[g]
        float a0 = 0.f, a1 = 0.f, a2 = 0.f, a3 = 0.f;
#pragma unroll
        for (int i = 0; i < 32; i++) {
            float4 hv = *(const float4*)&hs[4 * i];
            a0 = fmaf(w[4*i+0], hv.x, a0);
            a1 = fmaf(w[4*i+1], hv.y, a1);
            a2 = fmaf(w[4*i+2], hv.z, a2);
            a3 = fmaf(w[4*i+3], hv.w, a3);
        }
        gh[g] = (a0 + a1) + (a2 + a3) + bh;
        __syncthreads();

        if (g < HH) {
            float r  = sigf(xr + gh[g]);
            float z  = sigf(xz + gh[g + HH]);
            float n  = tanh_fast(xn + r * gh[g + 2*HH]);
            float hp = hs[g];
            float hn = fmaf(z, hp - n, n);   // (1-z)*n + z*h
            hs[g] = hn;
            out[baseOut + (size_t)tt * (2*HH) + g] = hn;
        }
        __syncthreads();

        xr = nxr; xz = nxz; xn = nxn;
    }
}

// ---------------------------------------------------------------------------
// Final FC: out[row][o] = dot(h[row][:256], fc_w[o][:]) + fc_b[o], o in {0,1}
// one warp per row.
// ---------------------------------------------------------------------------
__global__ __launch_bounds__(256) void fc_kernel(
    const float* __restrict__ h,
    const float* __restrict__ fw,   // [2][256]
    const float* __restrict__ fb,   // [2]
    float* __restrict__ out)        // [rows][2]
{
    int row  = blockIdx.x * 8 + (threadIdx.x >> 5);
    int lane = threadIdx.x & 31;
    const float* hp = h + (size_t)row * (2*HH);
    float a0 = 0.f, a1 = 0.f;
#pragma unroll
    for (int i = 0; i < 8; i++) {
        int k = lane + 32 * i;
        float v = hp[k];
        a0 = fmaf(v, fw[k],          a0);
        a1 = fmaf(v, fw[256 + k],    a1);
    }
#pragma unroll
    for (int off = 16; off; off >>= 1) {
        a0 += __shfl_xor_sync(0xffffffffu, a0, off);
        a1 += __shfl_xor_sync(0xffffffffu, a1, off);
    }
    if (lane == 0) {
        out[(size_t)row * 2 + 0] = a0 + fb[0];
        out[(size_t)row * 2 + 1] = a1 + fb[1];
    }
}

// ---------------------------------------------------------------------------
// Launch
// ---------------------------------------------------------------------------
extern "C" void kernel_launch(void* const* d_in, const int* in_sizes, int n_in,
                              void* d_out, int out_size)
{
    const float* x        = (const float*)d_in[0];
    const float* w_ih_l0  = (const float*)d_in[1];
    const float* w_hh_l0  = (const float*)d_in[2];
    const float* b_ih_l0  = (const float*)d_in[3];
    const float* b_hh_l0  = (const float*)d_in[4];
    const float* w_ih_l0r = (const float*)d_in[5];
    const float* w_hh_l0r = (const float*)d_in[6];
    const float* b_ih_l0r = (const float*)d_in[7];
    const float* b_hh_l0r = (const float*)d_in[8];
    const float* w_ih_l1  = (const float*)d_in[9];
    const float* w_hh_l1  = (const float*)d_in[10];
    const float* b_ih_l1  = (const float*)d_in[11];
    const float* b_hh_l1  = (const float*)d_in[12];
    const float* w_ih_l1r = (const float*)d_in[13];
    const float* w_hh_l1r = (const float*)d_in[14];
    const float* b_ih_l1r = (const float*)d_in[15];
    const float* b_hh_l1r = (const float*)d_in[16];
    const float* fc_w     = (const float*)d_in[17];
    const float* fc_b     = (const float*)d_in[18];
    float* out = (float*)d_out;

    float *xgF, *xgR, *hbuf;
    cudaGetSymbolAddress((void**)&xgF,  g_xgF);
    cudaGetSymbolAddress((void**)&xgR,  g_xgR);
    cudaGetSymbolAddress((void**)&hbuf, g_h);

    dim3 gGrid(BTR / 64, GG / 64);   // 2048 x 6
    dim3 gBlk(256);

    // Layer 0 input projections (K = 18)
    gemm_tn_bias<<<gGrid, gBlk>>>(x, DIN, w_ih_l0,  b_ih_l0,  xgF, GG, BTR, GG, DIN);
    gemm_tn_bias<<<gGrid, gBlk>>>(x, DIN, w_ih_l0r, b_ih_l0r, xgR, GG, BTR, GG, DIN);

    // Layer 0 scan (both directions)
    gru_scan<<<BB * 2, GG>>>(xgF, xgR, w_hh_l0, b_hh_l0, w_hh_l0r, b_hh_l0r, hbuf);

    // Layer 1 input projections (K = 256), reusing xg buffers
    gemm_tn_bias<<<gGrid, gBlk>>>(hbuf, 2*HH, w_ih_l1,  b_ih_l1,  xgF, GG, BTR, GG, 2*HH);
    gemm_tn_bias<<<gGrid, gBlk>>>(hbuf, 2*HH, w_ih_l1r, b_ih_l1r, xgR, GG, BTR, GG, 2*HH);

    // Layer 1 scan (overwrites hbuf with h1 — safe, GEMMs above are stream-ordered)
    gru_scan<<<BB * 2, GG>>>(xgF, xgR, w_hh_l1, b_hh_l1, w_hh_l1r, b_hh_l1r, hbuf);

    // Final FC
    fc_kernel<<<BTR / 8, 256>>>(hbuf, fc_w, fc_b, out);
}

// round 2
// speedup vs baseline: 1.0647x; 1.0647x over previous
#include <cuda_runtime.h>
#include <cuda_bf16.h>
#include <cstddef>

// Problem constants
#define BB   64
#define TT   2048
#define HH   128
#define GG   384     // 3*H
#define DIN  18
#define DOUT 2
#define BTR  (BB*TT)           // 131072 rows
#define GK   256               // layer-1 input width

// ---------------------------------------------------------------------------
// Scratch (device globals; no allocation allowed)
// ---------------------------------------------------------------------------
static __device__ float g_xgF[(size_t)BTR * GG];   // 201 MB
static __device__ float g_xgR[(size_t)BTR * GG];   // 201 MB
static __device__ float g_h  [(size_t)BTR * 2*HH]; // 134 MB (h0, then reused for h1)

// ---------------------------------------------------------------------------
// Helpers
// ---------------------------------------------------------------------------
__device__ __forceinline__ unsigned long long ffma2(unsigned long long a,
                                                    unsigned long long b,
                                                    unsigned long long c) {
    unsigned long long d;
    asm("fma.rn.f32x2 %0, %1, %2, %3;" : "=l"(d) : "l"(a), "l"(b), "l"(c));
    return d;
}
__device__ __forceinline__ unsigned long long d2u(double x) {
    return (unsigned long long)__double_as_longlong(x);
}
__device__ __forceinline__ float2 unpack2(unsigned long long v) {
    float2 r;
    asm("mov.b64 {%0, %1}, %2;" : "=f"(r.x), "=f"(r.y) : "l"(v));
    return r;
}
__device__ __forceinline__ float sigf(float x) {
    return 1.0f / (1.0f + __expf(-x));
}
__device__ __forceinline__ float tanh_fast(float x) {
    float xc = fminf(fmaxf(x, -20.0f), 20.0f);
    float e  = __expf(-2.0f * xc);
    return (1.0f - e) / (1.0f + e);
}

// ---------------------------------------------------------------------------
// Generic fp32 GEMM (used for the small K=18 projections):
// C[M][N] = A[M][K] * B[N][K]^T + bias[N].  64x64 tile, BK=16, 256 threads.
// ---------------------------------------------------------------------------
__global__ __launch_bounds__(256) void gemm_tn_bias(
    const float* __restrict__ A, int lda,
    const float* __restrict__ Bw,        // [N][K] row-major
    const float* __restrict__ bias,      // [N]
    float* __restrict__ C, int ldc,
    int M, int N, int K)
{
    const int BM = 64, BN = 64, BK = 16;
    const int PAD = 8;
    __shared__ __align__(16) float As[BK][BM + PAD];
    __shared__ __align__(16) float Bs[BK][BN + PAD];

    int tid = threadIdx.x;
    int tx = tid & 15;
    int ty = tid >> 4;
    int m0 = blockIdx.x * BM;
    int n0 = blockIdx.y * BN;

    float acc[4][4];
#pragma unroll
    for (int i = 0; i < 4; i++)
#pragma unroll
        for (int j = 0; j < 4; j++) acc[i][j] = 0.0f;

    int nkt = (K + BK - 1) / BK;
    for (int kt = 0; kt < nkt; kt++) {
        int k0 = kt * BK;
#pragma unroll
        for (int r = 0; r < 4; r++) {
            int idx = tid + r * 256;
            int m = idx >> 4;
            int k = idx & 15;
            float va = 0.0f, vb = 0.0f;
            if (k0 + k < K) {
                va = A[(size_t)(m0 + m) * lda + k0 + k];
                vb = Bw[(size_t)(n0 + m) * K + k0 + k];
            }
            As[k][m] = va;
            Bs[k][m] = vb;
        }
        __syncthreads();
#pragma unroll
        for (int k = 0; k < BK; k++) {
            float4 a = *(const float4*)&As[k][ty * 4];
            float4 b = *(const float4*)&Bs[k][tx * 4];
            float av[4] = {a.x, a.y, a.z, a.w};
            float bv[4] = {b.x, b.y, b.z, b.w};
#pragma unroll
            for (int i = 0; i < 4; i++)
#pragma unroll
                for (int j = 0; j < 4; j++)
                    acc[i][j] = fmaf(av[i], bv[j], acc[i][j]);
        }
        __syncthreads();
    }

#pragma unroll
    for (int i = 0; i < 4; i++) {
        int m = m0 + ty * 4 + i;
#pragma unroll
        for (int j = 0; j < 4; j++) {
            int n = n0 + tx * 4 + j;
            C[(size_t)m * ldc + n] = acc[i][j] + bias[n];
        }
    }
}

// ---------------------------------------------------------------------------
// K=256 GEMM with FFMA2:  C[BTR][384] = A[BTR][256] * Bw[384][256]^T + bias
// 128x128 tile, BK=16, 256 threads, 8x8 micro-tile.
// A stored in smem as duplicated pairs (a,a) so FFMA2 needs no packing MOVs;
// B read from smem as bit-packed f32 pairs via double2.
// M=131072 (mult of 128), N=384 (mult of 128), K=256 (mult of 16): no bounds.
// ---------------------------------------------------------------------------
__global__ __launch_bounds__(256, 2) void gemm128(
    const float* __restrict__ A,      // [BTR][256]
    const float* __restrict__ Bw,     // [384][256]
    const float* __restrict__ bias,   // [384]
    float* __restrict__ C)            // [BTR][384]
{
    __shared__ __align__(16) float2 As2[16][130];  // (a,a) dup pairs; row 1040B (16B-aligned)
    __shared__ __align__(16) float  Bs [16][136];  // row 544B (16B-aligned, 136%32==8 -> STS conflict-free)

    int tid = threadIdx.x;
    int tx = tid & 15;           // n group
    int ty = tid >> 4;           // m group
    int m0 = blockIdx.x * 128;
    int n0 = blockIdx.y * 128;

    unsigned long long acc[8][4];
#pragma unroll
    for (int i = 0; i < 8; i++)
#pragma unroll
        for (int j = 0; j < 4; j++) acc[i][j] = 0ull;

    float bias_r[8];
#pragma unroll
    for (int j = 0; j < 8; j++) bias_r[j] = bias[n0 + tx * 8 + j];

    int rowA = tid >> 2;          // 0..63
    int kq   = (tid & 3) * 4;     // 0,4,8,12

    for (int k0 = 0; k0 < GK; k0 += 16) {
#pragma unroll
        for (int p = 0; p < 2; p++) {
            int r = rowA + p * 64;
            float4 a = *(const float4*)&A [(size_t)(m0 + r) * GK + k0 + kq];
            float4 b = *(const float4*)&Bw[(size_t)(n0 + r) * GK + k0 + kq];
            As2[kq + 0][r] = make_float2(a.x, a.x);
            As2[kq + 1][r] = make_float2(a.y, a.y);
            As2[kq + 2][r] = make_float2(a.z, a.z);
            As2[kq + 3][r] = make_float2(a.w, a.w);
            Bs[kq + 0][r] = b.x;
            Bs[kq + 1][r] = b.y;
            Bs[kq + 2][r] = b.z;
            Bs[kq + 3][r] = b.w;
        }
        __syncthreads();
#pragma unroll
        for (int k = 0; k < 16; k++) {
            double2 bp0 = *(const double2*)&Bs[k][tx * 8];
            double2 bp1 = *(const double2*)&Bs[k][tx * 8 + 4];
            unsigned long long bb[4] = {d2u(bp0.x), d2u(bp0.y), d2u(bp1.x), d2u(bp1.y)};
            double2 ad0 = *(const double2*)&As2[k][ty * 8 + 0];
            double2 ad1 = *(const double2*)&As2[k][ty * 8 + 2];
            double2 ad2 = *(const double2*)&As2[k][ty * 8 + 4];
            double2 ad3 = *(const double2*)&As2[k][ty * 8 + 6];
            unsigned long long aa[8] = {d2u(ad0.x), d2u(ad0.y), d2u(ad1.x), d2u(ad1.y),
                                        d2u(ad2.x), d2u(ad2.y), d2u(ad3.x), d2u(ad3.y)};
#pragma unroll
            for (int i = 0; i < 8; i++)
#pragma unroll
                for (int j = 0; j < 4; j++)
                    acc[i][j] = ffma2(aa[i], bb[j], acc[i][j]);
        }
        __syncthreads();
    }

#pragma unroll
    for (int i = 0; i < 8; i++) {
        int m = m0 + ty * 8 + i;
        float2 p0 = unpack2(acc[i][0]);
        float2 p1 = unpack2(acc[i][1]);
        float2 p2 = unpack2(acc[i][2]);
        float2 p3 = unpack2(acc[i][3]);
        float4 o0 = make_float4(p0.x + bias_r[0], p0.y + bias_r[1],
                                p1.x + bias_r[2], p1.y + bias_r[3]);
        float4 o1 = make_float4(p2.x + bias_r[4], p2.y + bias_r[5],
                                p3.x + bias_r[6], p3.y + bias_r[7]);
        float* crow = &C[(size_t)m * GG + n0 + tx * 8];
        *(float4*)(crow)     = o0;
        *(float4*)(crow + 4) = o1;
    }
}

// ---------------------------------------------------------------------------
// GRU scan over T, both directions per layer in one launch.
// grid = 128 blocks: blockIdx.x = b*2 + dir. 384 threads, one gate each.
// w_hh row held as 64 register-resident packed f32 pairs; matvec via FFMA2.
// out: [B][T][256], fwd at cols [0,128), bwd at [128,256).
// ---------------------------------------------------------------------------
__global__ __launch_bounds__(384, 1) void gru_scan(
    const float* __restrict__ xgF, const float* __restrict__ xgR,
    const float* __restrict__ whhF, const float* __restrict__ bhhF,
    const float* __restrict__ whhR, const float* __restrict__ bhhR,
    float* __restrict__ out)
{
    int bb  = blockIdx.x >> 1;
    int dir = blockIdx.x & 1;
    const float* xg  = dir ? xgR  : xgF;
    const float* whh = dir ? whhR : whhF;
    const float* bhh = dir ? bhhR : bhhF;

    int g = threadIdx.x;

    // Register-resident packed weight row: 64 pairs (w[2i], w[2i+1])
    unsigned long long w2[64];
    {
        const double2* wrow = (const double2*)(whh + (size_t)g * HH);
#pragma unroll
        for (int i = 0; i < 32; i++) {
            double2 v = wrow[i];
            w2[2*i+0] = d2u(v.x);
            w2[2*i+1] = d2u(v.y);
        }
    }
    float bh = bhh[g];

    __shared__ __align__(16) float hs[HH];
    __shared__ float gh[GG];
    if (g < HH) hs[g] = 0.0f;

    const size_t baseXG  = (size_t)bb * TT * GG;
    const size_t baseOut = (size_t)bb * TT * (2*HH) + (size_t)dir * HH;

    // Prefetch xg for first step
    float xr = 0.f, xz = 0.f, xn = 0.f;
    {
        int tt0 = dir ? (TT - 1) : 0;
        if (g < HH) {
            const float* p = xg + baseXG + (size_t)tt0 * GG;
            xr = p[g]; xz = p[g + HH]; xn = p[g + 2*HH];
        }
    }
    __syncthreads();

    const double2* hsd = (const double2*)hs;

    for (int t = 0; t < TT; t++) {
        int tt = dir ? (TT - 1 - t) : t;

        // Prefetch next step's xg (latency hidden behind matvec)
        float nxr = 0.f, nxz = 0.f, nxn = 0.f;
        if (g < HH && t + 1 < TT) {
            int tn = dir ? (tt - 1) : (tt + 1);
            const float* p = xg + baseXG + (size_t)tn * GG;
            nxr = p[g]; nxz = p[g + HH]; nxn = p[g + 2*HH];
        }

        // gh[g] = dot(h, w_hh[g,:]) + b_hh[g]  -- 64 FFMA2
        unsigned long long a0 = 0ull, a1 = 0ull, a2 = 0ull, a3 = 0ull;
#pragma unroll
        for (int i = 0; i < 16; i++) {
            double2 h0 = hsd[2*i];
            double2 h1 = hsd[2*i+1];
            a0 = ffma2(w2[4*i+0], d2u(h0.x), a0);
            a1 = ffma2(w2[4*i+1], d2u(h0.y), a1);
            a2 = ffma2(w2[4*i+2], d2u(h1.x), a2);
            a3 = ffma2(w2[4*i+3], d2u(h1.y), a3);
        }
        float2 p0 = unpack2(a0), p1 = unpack2(a1), p2 = unpack2(a2), p3 = unpack2(a3);
        gh[g] = ((p0.x + p0.y) + (p1.x + p1.y)) + ((p2.x + p2.y) + (p3.x + p3.y)) + bh;
        __syncthreads();

        if (g < HH) {
            float r  = sigf(xr + gh[g]);
            float z  = sigf(xz + gh[g + HH]);
            float n  = tanh_fast(xn + r * gh[g + 2*HH]);
            float hp = hs[g];
            float hn = fmaf(z, hp - n, n);   // (1-z)*n + z*h
            hs[g] = hn;
            out[baseOut + (size_t)tt * (2*HH) + g] = hn;
        }
        __syncthreads();

        xr = nxr; xz = nxz; xn = nxn;
    }
}

// ---------------------------------------------------------------------------
// Final FC: out[row][o] = dot(h[row][:256], fc_w[o][:]) + fc_b[o], o in {0,1}
// ---------------------------------------------------------------------------
__global__ __launch_bounds__(256) void fc_kernel(
    const float* __restrict__ h,
    const float* __restrict__ fw,   // [2][256]
    const float* __restrict__ fb,   // [2]
    float* __restrict__ out)        // [rows][2]
{
    int row  = blockIdx.x * 8 + (threadIdx.x >> 5);
    int lane = threadIdx.x & 31;
    const float* hp = h + (size_t)row * (2*HH);
    float a0 = 0.f, a1 = 0.f;
#pragma unroll
    for (int i = 0; i < 8; i++) {
        int k = lane + 32 * i;
        float v = hp[k];
        a0 = fmaf(v, fw[k],       a0);
        a1 = fmaf(v, fw[256 + k], a1);
    }
#pragma unroll
    for (int off = 16; off; off >>= 1) {
        a0 += __shfl_xor_sync(0xffffffffu, a0, off);
        a1 += __shfl_xor_sync(0xffffffffu, a1, off);
    }
    if (lane == 0) {
        out[(size_t)row * 2 + 0] = a0 + fb[0];
        out[(size_t)row * 2 + 1] = a1 + fb[1];
    }
}

// ---------------------------------------------------------------------------
// Launch
// ---------------------------------------------------------------------------
extern "C" void kernel_launch(void* const* d_in, const int* in_sizes, int n_in,
                              void* d_out, int out_size)
{
    const float* x        = (const float*)d_in[0];
    const float* w_ih_l0  = (const float*)d_in[1];
    const float* w_hh_l0  = (const float*)d_in[2];
    const float* b_ih_l0  = (const float*)d_in[3];
    const float* b_hh_l0  = (const float*)d_in[4];
    const float* w_ih_l0r = (const float*)d_in[5];
    const float* w_hh_l0r = (const float*)d_in[6];
    const float* b_ih_l0r = (const float*)d_in[7];
    const float* b_hh_l0r = (const float*)d_in[8];
    const float* w_ih_l1  = (const float*)d_in[9];
    const float* w_hh_l1  = (const float*)d_in[10];
    const float* b_ih_l1  = (const float*)d_in[11];
    const float* b_hh_l1  = (const float*)d_in[12];
    const float* w_ih_l1r = (const float*)d_in[13];
    const float* w_hh_l1r = (const float*)d_in[14];
    const float* b_ih_l1r = (const float*)d_in[15];
    const float* b_hh_l1r = (const float*)d_in[16];
    const float* fc_w     = (const float*)d_in[17];
    const float* fc_b     = (const float*)d_in[18];
    float* out = (float*)d_out;

    float *xgF, *xgR, *hbuf;
    cudaGetSymbolAddress((void**)&xgF,  g_xgF);
    cudaGetSymbolAddress((void**)&xgR,  g_xgR);
    cudaGetSymbolAddress((void**)&hbuf, g_h);

    // Layer 0 input projections (K = 18): generic SIMT GEMM
    dim3 gGrid(BTR / 64, GG / 64);   // 2048 x 6
    gemm_tn_bias<<<gGrid, 256>>>(x, DIN, w_ih_l0,  b_ih_l0,  xgF, GG, BTR, GG, DIN);
    gemm_tn_bias<<<gGrid, 256>>>(x, DIN, w_ih_l0r, b_ih_l0r, xgR, GG, BTR, GG, DIN);

    // Layer 0 scan (both directions)
    gru_scan<<<BB * 2, GG>>>(xgF, xgR, w_hh_l0, b_hh_l0, w_hh_l0r, b_hh_l0r, hbuf);

    // Layer 1 input projections (K = 256): FFMA2 GEMM
    dim3 g2Grid(BTR / 128, GG / 128);  // 1024 x 3
    gemm128<<<g2Grid, 256>>>(hbuf, w_ih_l1,  b_ih_l1,  xgF);
    gemm128<<<g2Grid, 256>>>(hbuf, w_ih_l1r, b_ih_l1r, xgR);

    // Layer 1 scan
    gru_scan<<<BB * 2, GG>>>(xgF, xgR, w_hh_l1, b_hh_l1, w_hh_l1r, b_hh_l1r, hbuf);

    // Final FC
    fc_kernel<<<BTR / 8, 256>>>(hbuf, fc_w, fc_b, out);
}